// round 14
// baseline (speedup 1.0000x reference)
#include <cuda_runtime.h>
#include <cuda_fp16.h>
#include <cstdint>
#include <math.h>

#define B_ROWS   16384
#define DATA_DIM 4096
#define Z_DIM    512
#define H_DIM    400
#define H_PAD    416     // H padded to multiple of 32 (K-chunk); cols 400-415 stay zero
#define N1_PAD   512     // H padded to multiple of 128 (N-tile grid)
#define GRID_P   296     // persistent grid: 148 SMs x 2 CTAs

typedef __half f16;

// ---------------- scratch (allocation-free device globals, zero-init) ------
__device__ alignas(256) f16 g_xq [B_ROWS * DATA_DIM];
__device__ alignas(256) f16 g_h1q[B_ROWS * H_PAD];     // pad cols stay zero
__device__ alignas(256) f16 g_zq [B_ROWS * Z_DIM];
__device__ alignas(256) f16 g_h3q[B_ROWS * H_PAD];
__device__ float g_std[B_ROWS];
// transposed + split weights [Npad][Kpad] f16 hi/lo (K-major), zero padded
__device__ alignas(256) f16 g_W1h [N1_PAD * DATA_DIM], g_W1l [N1_PAD * DATA_DIM];
__device__ alignas(256) f16 g_W21h[Z_DIM * H_PAD],     g_W21l[Z_DIM * H_PAD];
__device__ alignas(256) f16 g_W3h [N1_PAD * Z_DIM],    g_W3l [N1_PAD * Z_DIM];
__device__ alignas(256) f16 g_W4h [DATA_DIM * H_PAD],  g_W4l [DATA_DIM * H_PAD];

// ---------------- PTX helpers ----------------------------------------------
__device__ __forceinline__ uint32_t smem_u32(const void* p) {
    uint32_t a;
    asm("{ .reg .u64 t; cvta.to.shared.u64 t, %1; cvt.u32.u64 %0, t; }"
        : "=r"(a) : "l"(p));
    return a;
}
__device__ __forceinline__ void cp16(uint32_t dst, const void* src) {
    asm volatile("cp.async.cg.shared.global [%0], [%1], 16;"
                 :: "r"(dst), "l"(src) : "memory");
}
__device__ __forceinline__ void cp_commit() {
    asm volatile("cp.async.commit_group;" ::: "memory");
}
template <int N> __device__ __forceinline__ void cp_wait() {
    asm volatile("cp.async.wait_group %0;" :: "n"(N) : "memory");
}
#define LDSM4(R, addr) \
    asm volatile("ldmatrix.sync.aligned.m8n8.x4.shared.b16 {%0,%1,%2,%3}, [%4];" \
                 : "=r"((R)[0]), "=r"((R)[1]), "=r"((R)[2]), "=r"((R)[3])      \
                 : "r"(addr))
#define MMA16816(C, A, B0, B1) \
    asm volatile("mma.sync.aligned.m16n8k16.row.col.f32.f16.f16.f32 "          \
                 "{%0,%1,%2,%3}, {%4,%5,%6,%7}, {%8,%9}, {%0,%1,%2,%3};"       \
                 : "+f"((C)[0]), "+f"((C)[1]), "+f"((C)[2]), "+f"((C)[3])      \
                 : "r"((A)[0]), "r"((A)[1]), "r"((A)[2]), "r"((A)[3]),         \
                   "r"(B0), "r"(B1))

// smem stage: 3 matrices [128 rows][32 f16 + 8 pad] (80 B rows, 16B aligned)
#define ROWB     80
#define MAT_SZ   10240                 // 128*80
#define OFF_A    0
#define OFF_BH   10240
#define OFF_BL   20480
#define STAGE_SZ 30720
#define SMEM_TOT (2 * STAGE_SZ)       // 61440 -> two CTAs per SM

// ---------------- stage loader: K-chunk 32, cp.async 16B ------------------
__device__ __forceinline__ void ld_stage(
    uint32_t s0, int tid,
    const f16* __restrict__ Aq, size_t arow0, int lda,
    const f16* __restrict__ Bh, const f16* __restrict__ Bl,
    size_t brow0, int ldb, int k0)
{
#pragma unroll
    for (int j = 0; j < 6; j++) {
        const int idx = tid + j * 256;          // 0..1535
        const int mat = idx >> 9;               // 0:A 1:Bh 2:Bl
        const int rem = idx & 511;
        const int row = rem >> 2;               // 0..127
        const int ch  = rem & 3;                // 16B chunk (8 f16)
        const f16* src;
        if (mat == 0)      src = Aq + (arow0 + row) * (size_t)lda + k0 + ch * 8;
        else if (mat == 1) src = Bh + (brow0 + row) * (size_t)ldb + k0 + ch * 8;
        else               src = Bl + (brow0 + row) * (size_t)ldb + k0 + ch * 8;
        cp16(s0 + mat * MAT_SZ + row * ROWB + ch * 16, src);
    }
}

// ---------------- per-ks fragment load + 32 MMAs ---------------------------
__device__ __forceinline__ void compute_ks(
    uint32_t st, int ks, int wm, int wn, int lane, float (&acc)[4][4][4])
{
    uint32_t a[4][4], bh[4][2], bl[4][2];
#pragma unroll
    for (int mt = 0; mt < 4; mt++) {
        const int row = wm * 64 + mt * 16 + (lane & 15);
        const uint32_t aoff = row * ROWB + ks * 32 + ((lane >> 4) << 4);
        LDSM4(a[mt], st + OFF_A + aoff);
    }
#pragma unroll
    for (int nt = 0; nt < 2; nt++) {
        const int row = wn * 32 + nt * 16 + (lane & 7) + ((lane >> 4) << 3);
        const uint32_t boff = row * ROWB + ks * 32 + ((lane >> 3) & 1) * 16;
        uint32_t r[4];
        LDSM4(r, st + OFF_BH + boff);
        bh[nt * 2][0] = r[0]; bh[nt * 2][1] = r[1];
        bh[nt * 2 + 1][0] = r[2]; bh[nt * 2 + 1][1] = r[3];
        LDSM4(r, st + OFF_BL + boff);
        bl[nt * 2][0] = r[0]; bl[nt * 2][1] = r[1];
        bl[nt * 2 + 1][0] = r[2]; bl[nt * 2 + 1][1] = r[3];
    }
    // hi pass then lo pass: same-acc MMAs separated by 16 instructions
#pragma unroll
    for (int mt = 0; mt < 4; mt++)
#pragma unroll
        for (int n = 0; n < 4; n++)
            MMA16816(acc[mt][n], a[mt], bh[n][0], bh[n][1]);
#pragma unroll
    for (int mt = 0; mt < 4; mt++)
#pragma unroll
        for (int n = 0; n < 4; n++)
            MMA16816(acc[mt][n], a[mt], bl[n][0], bl[n][1]);
}

// ---------------- fp16-activation / split-fp16-weight GEMM -----------------
// Persistent: GRID_P CTAs loop over (nbx x nby) 128x128 tiles, bx fastest.
// Double-buffer parity carried across tiles via global chunk counter gc.
// EPI: 0 none, 1 relu, 2 sigmoid.  HOUT: 1 -> store f16, 0 -> fp32.
template <int EPI, int HOUT>
__global__ __launch_bounds__(256, 2) void gemm_mma(
    const f16* __restrict__ Aq, int lda,
    const f16* __restrict__ Bh, const f16* __restrict__ Bl, int ldb,
    const float* __restrict__ bias,
    float* __restrict__ Cf, f16* __restrict__ Ch,
    int ldc, int nout, int K, int nbx, int ntiles)
{
    extern __shared__ char smem[];
    const uint32_t sb = smem_u32(smem);
    const int tid  = threadIdx.x;
    const int wid  = tid >> 5, lane = tid & 31;
    const int wm   = wid & 1,  wn   = wid >> 1;   // 2 M-warps x 4 N-warps
    const int NC = K >> 5;                        // 32-wide K chunks
    int gc = 0;                                   // global chunk counter

    for (int t = blockIdx.x; t < ntiles; t += GRID_P) {
        const int bx = t % nbx, by = t / nbx;
        const size_t arow0 = (size_t)by * 128;
        const size_t brow0 = (size_t)bx * 128;
        const bool active = (bx * 128 + wn * 32) < nout;   // warp-uniform

        float acc[4][4][4];
#pragma unroll
        for (int a = 0; a < 4; a++)
#pragma unroll
            for (int b = 0; b < 4; b++)
#pragma unroll
                for (int c = 0; c < 4; c++) acc[a][b][c] = 0.0f;

        ld_stage(sb + (gc & 1) * STAGE_SZ, tid,
                 Aq, arow0, lda, Bh, Bl, brow0, ldb, 0);
        cp_commit();

        for (int i = 0; i < NC; i++, gc++) {
            cp_wait<0>();
            __syncthreads();                      // single barrier per chunk

            const uint32_t st = sb + (gc & 1) * STAGE_SZ;
            if (active) compute_ks(st, 0, wm, wn, lane, acc);

            if (i + 1 < NC) {                     // mid-chunk prefetch
                ld_stage(sb + ((gc + 1) & 1) * STAGE_SZ, tid,
                         Aq, arow0, lda, Bh, Bl, brow0, ldb, (i + 1) << 5);
                cp_commit();
            }

            if (active) compute_ks(st, 1, wm, wn, lane, acc);
        }

        // ---- epilogue: bias + activation, direct register stores ----
        if (active) {
#pragma unroll
        for (int n8 = 0; n8 < 4; n8++) {
            const int gcn = bx * 128 + wn * 32 + n8 * 8 + (lane & 3) * 2;
            if (gcn >= nout) continue;
            const float bia0 = bias[gcn], bia1 = bias[gcn + 1];
#pragma unroll
            for (int mt = 0; mt < 4; mt++) {
                const size_t r0 = arow0 + wm * 64 + mt * 16 + (lane >> 2);
                float v[4];
                v[0] = acc[mt][n8][0] + bia0;  v[1] = acc[mt][n8][1] + bia1;
                v[2] = acc[mt][n8][2] + bia0;  v[3] = acc[mt][n8][3] + bia1;
#pragma unroll
                for (int q = 0; q < 4; q++) {
                    if (EPI == 1) v[q] = fmaxf(v[q], 0.0f);
                    if (EPI == 2) v[q] = 1.0f / (1.0f + __expf(-v[q]));
                }
                if (HOUT) {
                    __half2 p0 = __floats2half2_rn(v[0], v[1]);
                    __half2 p1 = __floats2half2_rn(v[2], v[3]);
                    *reinterpret_cast<__half2*>(Ch + r0 * ldc + gcn)       = p0;
                    *reinterpret_cast<__half2*>(Ch + (r0 + 8) * ldc + gcn) = p1;
                } else {
                    float2 p0, p1;
                    p0.x = v[0]; p0.y = v[1];  p1.x = v[2]; p1.y = v[3];
                    *reinterpret_cast<float2*>(Cf + r0 * ldc + gcn)       = p0;
                    *reinterpret_cast<float2*>(Cf + (r0 + 8) * ldc + gcn) = p1;
                }
            }
        }
        }
    }
}

// ---------------- x -> fp16 (elementwise) -----------------------------------
__global__ void cvt_x(const float4* __restrict__ x, uint4* __restrict__ xq)
{
    const size_t i = (size_t)blockIdx.x * blockDim.x + threadIdx.x;
    const float4 a = x[i * 2];
    const float4 b = x[i * 2 + 1];
    __half2 h0 = __floats2half2_rn(a.x, a.y);
    __half2 h1 = __floats2half2_rn(a.z, a.w);
    __half2 h2 = __floats2half2_rn(b.x, b.y);
    __half2 h3 = __floats2half2_rn(b.z, b.w);
    uint4 u;
    u.x = *reinterpret_cast<uint32_t*>(&h0);
    u.y = *reinterpret_cast<uint32_t*>(&h1);
    u.z = *reinterpret_cast<uint32_t*>(&h2);
    u.w = *reinterpret_cast<uint32_t*>(&h3);
    xq[i] = u;
}

// ---------------- weight prep: transpose [K,N] f32 -> [Np][Kp] f16 hi/lo ---
__global__ void prep_weight(const float* __restrict__ W, int K, int N,
                            f16* __restrict__ Wh, f16* __restrict__ Wl,
                            int Kp, int Np)
{
    __shared__ float t[32][33];
    const int k0 = blockIdx.x * 32, n0 = blockIdx.y * 32;
    const int tx = threadIdx.x, ty = threadIdx.y;     // (32, 8)
#pragma unroll
    for (int j = 0; j < 4; j++) {
        const int k = k0 + ty + j * 8, n = n0 + tx;
        t[ty + j * 8][tx] = (k < K && n < N) ? W[(size_t)k * N + n] : 0.0f;
    }
    __syncthreads();
#pragma unroll
    for (int j = 0; j < 4; j++) {
        const int n = n0 + ty + j * 8, k = k0 + tx;
        if (n < Np && k < Kp) {
            const float v = t[tx][ty + j * 8];
            const f16 h = __float2half_rn(v);
            Wh[(size_t)n * Kp + k] = h;
            Wl[(size_t)n * Kp + k] = __float2half_rn(v - __half2float(h));
        }
    }
}

// ------------- per-row heads: rho = tanh(h1@W22+b22), logs = h1@W23+b23 ----
__global__ void rho_logs_kernel(const f16* __restrict__ h1q,
                                const float* __restrict__ W22,
                                const float* __restrict__ b22,
                                const float* __restrict__ W23,
                                const float* __restrict__ b23,
                                float* __restrict__ rho_out,
                                float* __restrict__ logs_out)
{
    const int row  = blockIdx.x * blockDim.y + threadIdx.y;
    const int lane = threadIdx.x;
    const size_t base = (size_t)row * H_PAD;

    float a = 0.f, b = 0.f;
    for (int i = lane; i < H_DIM; i += 32) {
        const float h = __half2float(h1q[base + i]);
        a = fmaf(h, W22[i], a);
        b = fmaf(h, W23[i], b);
    }
#pragma unroll
    for (int o = 16; o > 0; o >>= 1) {
        a += __shfl_xor_sync(0xffffffffu, a, o);
        b += __shfl_xor_sync(0xffffffffu, b, o);
    }
    if (lane == 0) {
        const float logs = b + b23[0];
        rho_out[row]  = tanhf(a + b22[0]);
        logs_out[row] = logs;
        g_std[row]    = sqrtf(expf(logs));
    }
}

// ------------- z = cumsum(eps * std, axis=1) + mu, warp per row ------------
__global__ __launch_bounds__(256) void scan_kernel(
    const float* __restrict__ eps, const float* __restrict__ mu,
    f16* __restrict__ zq)
{
    const int warp = threadIdx.x >> 5, lane = threadIdx.x & 31;
    const int row  = blockIdx.x * 8 + warp;
    const float s  = g_std[row];
    const size_t base = (size_t)row * Z_DIM + lane * 16;

    float v[16];
#pragma unroll
    for (int q = 0; q < 4; q++) {
        const float4 e = *reinterpret_cast<const float4*>(eps + base + q * 4);
        v[q * 4 + 0] = e.x * s;  v[q * 4 + 1] = e.y * s;
        v[q * 4 + 2] = e.z * s;  v[q * 4 + 3] = e.w * s;
    }
#pragma unroll
    for (int q = 1; q < 16; q++) v[q] += v[q - 1];
    float tot = v[15];
#pragma unroll
    for (int o = 1; o < 32; o <<= 1) {
        const float n = __shfl_up_sync(0xffffffffu, tot, o);
        if (lane >= o) tot += n;
    }
    const float off = tot - v[15];        // exclusive prefix for this lane

    __half2 hp[8];
#pragma unroll
    for (int q = 0; q < 4; q++) {
        const float4 m = *reinterpret_cast<const float4*>(mu + base + q * 4);
        hp[q * 2]     = __floats2half2_rn(v[q * 4 + 0] + off + m.x,
                                          v[q * 4 + 1] + off + m.y);
        hp[q * 2 + 1] = __floats2half2_rn(v[q * 4 + 2] + off + m.z,
                                          v[q * 4 + 3] + off + m.w);
    }
    *reinterpret_cast<uint4*>(zq + base)     = *reinterpret_cast<uint4*>(&hp[0]);
    *reinterpret_cast<uint4*>(zq + base + 8) = *reinterpret_cast<uint4*>(&hp[4]);
}

// ---------------------------------------------------------------------------
extern "C" void kernel_launch(void* const* d_in, const int* in_sizes, int n_in,
                              void* d_out, int out_size)
{
    const float* x   = (const float*)d_in[0];
    const float* eps = (const float*)d_in[1];
    const float* W1  = (const float*)d_in[2];
    const float* b1  = (const float*)d_in[3];
    const float* W21 = (const float*)d_in[4];
    const float* b21 = (const float*)d_in[5];
    const float* W22 = (const float*)d_in[6];
    const float* b22 = (const float*)d_in[7];
    const float* W23 = (const float*)d_in[8];
    const float* b23 = (const float*)d_in[9];
    const float* W3  = (const float*)d_in[10];
    const float* b3  = (const float*)d_in[11];
    const float* W4  = (const float*)d_in[12];
    const float* b4  = (const float*)d_in[13];

    float* out       = (float*)d_out;
    float* out_recon = out;                                    // [B, 4096]
    float* out_mu    = out_recon + (size_t)B_ROWS * DATA_DIM;  // [B, 512]
    float* out_rho   = out_mu    + (size_t)B_ROWS * Z_DIM;     // [B, 1]
    float* out_logs  = out_rho   + B_ROWS;                     // [B, 1]

    f16 *xq, *h1q, *zq, *h3q;
    f16 *W1h, *W1l, *W21h, *W21l, *W3h, *W3l, *W4h, *W4l;
    cudaGetSymbolAddress((void**)&xq,   g_xq);
    cudaGetSymbolAddress((void**)&h1q,  g_h1q);
    cudaGetSymbolAddress((void**)&zq,   g_zq);
    cudaGetSymbolAddress((void**)&h3q,  g_h3q);
    cudaGetSymbolAddress((void**)&W1h,  g_W1h);
    cudaGetSymbolAddress((void**)&W1l,  g_W1l);
    cudaGetSymbolAddress((void**)&W21h, g_W21h);
    cudaGetSymbolAddress((void**)&W21l, g_W21l);
    cudaGetSymbolAddress((void**)&W3h,  g_W3h);
    cudaGetSymbolAddress((void**)&W3l,  g_W3l);
    cudaGetSymbolAddress((void**)&W4h,  g_W4h);
    cudaGetSymbolAddress((void**)&W4l,  g_W4l);

    cudaFuncSetAttribute(gemm_mma<1, 1>, cudaFuncAttributeMaxDynamicSharedMemorySize, SMEM_TOT);
    cudaFuncSetAttribute(gemm_mma<0, 0>, cudaFuncAttributeMaxDynamicSharedMemorySize, SMEM_TOT);
    cudaFuncSetAttribute(gemm_mma<2, 0>, cudaFuncAttributeMaxDynamicSharedMemorySize, SMEM_TOT);

    const dim3 pb(32, 8);

    // idx0: x -> fp16
    cvt_x<<<(B_ROWS * DATA_DIM / 8) / 256, 256>>>(
        (const float4*)x, (uint4*)xq);
    // idx1, idx2: weights needed by gemm1/gemm2
    prep_weight<<<dim3(DATA_DIM / 32, N1_PAD / 32), pb>>>(W1,  DATA_DIM, H_DIM, W1h,  W1l,  DATA_DIM, N1_PAD);
    prep_weight<<<dim3(H_PAD / 32,    Z_DIM / 32),  pb>>>(W21, H_DIM,    Z_DIM, W21h, W21l, H_PAD,    Z_DIM);

    // idx3 (ncu capture slot): h1 = relu(x @ W1 + b1) -> f16
    gemm_mma<1, 1><<<GRID_P, 256, SMEM_TOT>>>(
        xq, DATA_DIM, W1h, W1l, DATA_DIM, b1,
        nullptr, h1q, H_PAD, H_DIM, DATA_DIM,
        N1_PAD / 128, (N1_PAD / 128) * (B_ROWS / 128));

    // idx4: rho / logs / std
    rho_logs_kernel<<<B_ROWS / 8, dim3(32, 8)>>>(
        h1q, W22, b22, W23, b23, out_rho, out_logs);

    // idx5: mu = h1 @ W21 + b21 -> fp32 output
    gemm_mma<0, 0><<<GRID_P, 256, SMEM_TOT>>>(
        h1q, H_PAD, W21h, W21l, H_PAD, b21,
        out_mu, nullptr, Z_DIM, Z_DIM, H_PAD,
        Z_DIM / 128, (Z_DIM / 128) * (B_ROWS / 128));

    // idx6: z = cumsum(eps*std) + mu -> f16 (warp per row)
    scan_kernel<<<B_ROWS / 8, 256>>>(eps, out_mu, zq);

    // idx7: W3 prep, idx8: h3 = relu(z @ W3 + b3) -> f16
    prep_weight<<<dim3(Z_DIM / 32, N1_PAD / 32), pb>>>(W3, Z_DIM, H_DIM, W3h, W3l, Z_DIM, N1_PAD);
    gemm_mma<1, 1><<<GRID_P, 256, SMEM_TOT>>>(
        zq, Z_DIM, W3h, W3l, Z_DIM, b3,
        nullptr, h3q, H_PAD, H_DIM, Z_DIM,
        N1_PAD / 128, (N1_PAD / 128) * (B_ROWS / 128));

    // idx9: W4 prep, idx10: recon = sigmoid(h3 @ W4 + b4) -> fp32 output
    prep_weight<<<dim3(H_PAD / 32, DATA_DIM / 32), pb>>>(W4, H_DIM, DATA_DIM, W4h, W4l, H_PAD, DATA_DIM);
    gemm_mma<2, 0><<<GRID_P, 256, SMEM_TOT>>>(
        h3q, H_PAD, W4h, W4l, H_PAD, b4,
        out_recon, nullptr, DATA_DIM, DATA_DIM, H_PAD,
        DATA_DIM / 128, (DATA_DIM / 128) * (B_ROWS / 128));
}

// round 16
// speedup vs baseline: 1.0548x; 1.0548x over previous
#include <cuda_runtime.h>
#include <cuda_fp16.h>
#include <cstdint>
#include <math.h>

#define B_ROWS   16384
#define DATA_DIM 4096
#define Z_DIM    512
#define H_DIM    400
#define H_PAD    416     // H padded to multiple of 32 (K-chunk); cols 400-415 stay zero
#define N1_PAD   512     // H padded to multiple of 128 (N-tile grid)

typedef __half f16;

// ---------------- scratch (allocation-free device globals, zero-init) ------
__device__ alignas(256) f16 g_xq [B_ROWS * DATA_DIM];
__device__ alignas(256) f16 g_h1q[B_ROWS * H_PAD];     // pad cols stay zero
__device__ alignas(256) f16 g_zq [B_ROWS * Z_DIM];
__device__ alignas(256) f16 g_h3q[B_ROWS * H_PAD];
__device__ float g_std[B_ROWS];
// transposed + split weights [Npad][Kpad] f16 hi/lo (K-major), zero padded
__device__ alignas(256) f16 g_W1h [N1_PAD * DATA_DIM], g_W1l [N1_PAD * DATA_DIM];
__device__ alignas(256) f16 g_W21h[Z_DIM * H_PAD],     g_W21l[Z_DIM * H_PAD];
__device__ alignas(256) f16 g_W3h [N1_PAD * Z_DIM],    g_W3l [N1_PAD * Z_DIM];
__device__ alignas(256) f16 g_W4h [DATA_DIM * H_PAD],  g_W4l [DATA_DIM * H_PAD];

// ---------------- PTX helpers ----------------------------------------------
__device__ __forceinline__ uint32_t smem_u32(const void* p) {
    uint32_t a;
    asm("{ .reg .u64 t; cvta.to.shared.u64 t, %1; cvt.u32.u64 %0, t; }"
        : "=r"(a) : "l"(p));
    return a;
}
__device__ __forceinline__ void cp16(uint32_t dst, const void* src) {
    asm volatile("cp.async.cg.shared.global [%0], [%1], 16;"
                 :: "r"(dst), "l"(src) : "memory");
}
__device__ __forceinline__ void cp_commit() {
    asm volatile("cp.async.commit_group;" ::: "memory");
}
template <int N> __device__ __forceinline__ void cp_wait() {
    asm volatile("cp.async.wait_group %0;" :: "n"(N) : "memory");
}
#define LDSM4(R, addr) \
    asm volatile("ldmatrix.sync.aligned.m8n8.x4.shared.b16 {%0,%1,%2,%3}, [%4];" \
                 : "=r"((R)[0]), "=r"((R)[1]), "=r"((R)[2]), "=r"((R)[3])      \
                 : "r"(addr))
#define MMA16816(C, A, B0, B1) \
    asm volatile("mma.sync.aligned.m16n8k16.row.col.f32.f16.f16.f32 "          \
                 "{%0,%1,%2,%3}, {%4,%5,%6,%7}, {%8,%9}, {%0,%1,%2,%3};"       \
                 : "+f"((C)[0]), "+f"((C)[1]), "+f"((C)[2]), "+f"((C)[3])      \
                 : "r"((A)[0]), "r"((A)[1]), "r"((A)[2]), "r"((A)[3]),         \
                   "r"(B0), "r"(B1))

// stage geometry (templated on K-chunk KC): 3 matrices [128 rows][KC f16 + 8 pad]
template <int KC> struct Geo {
    static constexpr int ROWB  = KC * 2 + 16;       // bytes per row (bank step 4)
    static constexpr int MATS  = 128 * ROWB;
    static constexpr int STAGE = 3 * MATS;          // A, Bh, Bl
    static constexpr int CPR   = KC / 8;            // 16B chunks per row
};

// ---------------- stage loader: cp.async 16B -------------------------------
template <int KC>
__device__ __forceinline__ void ld_stage(
    uint32_t s0, int tid,
    const f16* __restrict__ Aq, size_t arow0, int lda,
    const f16* __restrict__ Bh, const f16* __restrict__ Bl,
    size_t brow0, int ldb, int k0)
{
    constexpr int CPR = Geo<KC>::CPR;
    constexpr int TOT = 3 * 128 * CPR;
#pragma unroll
    for (int j = 0; j < TOT / 256; j++) {
        const int idx = tid + j * 256;
        const int mat = idx / (128 * CPR);          // 0:A 1:Bh 2:Bl
        const int rem = idx % (128 * CPR);
        const int row = rem / CPR;
        const int ch  = rem % CPR;
        const f16* src;
        if (mat == 0)      src = Aq + (arow0 + row) * (size_t)lda + k0 + ch * 8;
        else if (mat == 1) src = Bh + (brow0 + row) * (size_t)ldb + k0 + ch * 8;
        else               src = Bl + (brow0 + row) * (size_t)ldb + k0 + ch * 8;
        cp16(s0 + mat * Geo<KC>::MATS + row * Geo<KC>::ROWB + ch * 16, src);
    }
}

// ---------------- per-k16-step fragment load + 32 MMAs ---------------------
template <int KC>
__device__ __forceinline__ void compute_ks(
    uint32_t st, int ks, int wm, int wn, int lane, float (&acc)[4][4][4])
{
    constexpr int ROWB = Geo<KC>::ROWB;
    constexpr int MATS = Geo<KC>::MATS;
    uint32_t a[4][4], bh[4][2], bl[4][2];
#pragma unroll
    for (int mt = 0; mt < 4; mt++) {
        const int row = wm * 64 + mt * 16 + (lane & 15);
        const uint32_t aoff = row * ROWB + ks * 32 + ((lane >> 4) << 4);
        LDSM4(a[mt], st + aoff);
    }
#pragma unroll
    for (int nt = 0; nt < 2; nt++) {
        const int row = wn * 32 + nt * 16 + (lane & 7) + ((lane >> 4) << 3);
        const uint32_t boff = row * ROWB + ks * 32 + ((lane >> 3) & 1) * 16;
        uint32_t r[4];
        LDSM4(r, st + MATS + boff);
        bh[nt * 2][0] = r[0]; bh[nt * 2][1] = r[1];
        bh[nt * 2 + 1][0] = r[2]; bh[nt * 2 + 1][1] = r[3];
        LDSM4(r, st + 2 * MATS + boff);
        bl[nt * 2][0] = r[0]; bl[nt * 2][1] = r[1];
        bl[nt * 2 + 1][0] = r[2]; bl[nt * 2 + 1][1] = r[3];
    }
#pragma unroll
    for (int mt = 0; mt < 4; mt++)
#pragma unroll
        for (int n = 0; n < 4; n++) {
            MMA16816(acc[mt][n], a[mt], bh[n][0], bh[n][1]);
            MMA16816(acc[mt][n], a[mt], bl[n][0], bl[n][1]);
        }
}

// ---------------- fp16-activation / split-fp16-weight GEMM -----------------
// C[128*by.., 128*bx..] = epi(A @ (Bh+Bl)^T + bias)
// KC: K-chunk width (32 or 64). Double-buffered; one barrier per chunk;
// next-chunk cp.async issued mid-chunk. EPI: 0 none, 1 relu, 2 sigmoid.
// HOUT: 1 -> store f16, 0 -> fp32.
template <int EPI, int HOUT, int KC>
__global__ __launch_bounds__(256, 2) void gemm_mma(
    const f16* __restrict__ Aq, int lda,
    const f16* __restrict__ Bh, const f16* __restrict__ Bl, int ldb,
    const float* __restrict__ bias,
    float* __restrict__ Cf, f16* __restrict__ Ch,
    int ldc, int nout, int K)
{
    constexpr int STAGE = Geo<KC>::STAGE;
    constexpr int NKS   = KC / 16;
    extern __shared__ char smem[];
    const uint32_t sb = smem_u32(smem);
    const int tid  = threadIdx.x;
    const int wid  = tid >> 5, lane = tid & 31;
    const int wm   = wid & 1,  wn   = wid >> 1;   // 2 M-warps x 4 N-warps
    const int bx   = blockIdx.x, by = blockIdx.y;
    const size_t arow0 = (size_t)by * 128;
    const size_t brow0 = (size_t)bx * 128;
    const bool active = (bx * 128 + wn * 32) < nout;   // warp-uniform

    float acc[4][4][4];
#pragma unroll
    for (int a = 0; a < 4; a++)
#pragma unroll
        for (int b = 0; b < 4; b++)
#pragma unroll
            for (int c = 0; c < 4; c++) acc[a][b][c] = 0.0f;

    const int NC = K / KC;
    ld_stage<KC>(sb, tid, Aq, arow0, lda, Bh, Bl, brow0, ldb, 0);
    cp_commit();

    for (int i = 0; i < NC; i++) {
        cp_wait<0>();
        __syncthreads();                          // single barrier per chunk

        const uint32_t st = sb + (i & 1) * STAGE;
        if (active) {
#pragma unroll
            for (int ks = 0; ks < NKS / 2; ks++)
                compute_ks<KC>(st, ks, wm, wn, lane, acc);
        }

        if (i + 1 < NC) {                         // mid-chunk prefetch
            ld_stage<KC>(sb + ((i + 1) & 1) * STAGE, tid,
                         Aq, arow0, lda, Bh, Bl, brow0, ldb, (i + 1) * KC);
            cp_commit();
        }

        if (active) {
#pragma unroll
            for (int ks = NKS / 2; ks < NKS; ks++)
                compute_ks<KC>(st, ks, wm, wn, lane, acc);
        }
    }

    // ---- epilogue: bias + activation, direct register stores ----
    if (active) {
#pragma unroll
    for (int n8 = 0; n8 < 4; n8++) {
        const int gc = bx * 128 + wn * 32 + n8 * 8 + (lane & 3) * 2;
        if (gc >= nout) continue;
        const float bia0 = bias[gc], bia1 = bias[gc + 1];
#pragma unroll
        for (int mt = 0; mt < 4; mt++) {
            const size_t r0 = arow0 + wm * 64 + mt * 16 + (lane >> 2);
            float v[4];
            v[0] = acc[mt][n8][0] + bia0;  v[1] = acc[mt][n8][1] + bia1;
            v[2] = acc[mt][n8][2] + bia0;  v[3] = acc[mt][n8][3] + bia1;
#pragma unroll
            for (int q = 0; q < 4; q++) {
                if (EPI == 1) v[q] = fmaxf(v[q], 0.0f);
                if (EPI == 2) v[q] = 1.0f / (1.0f + __expf(-v[q]));
            }
            if (HOUT) {
                __half2 p0 = __floats2half2_rn(v[0], v[1]);
                __half2 p1 = __floats2half2_rn(v[2], v[3]);
                *reinterpret_cast<__half2*>(Ch + r0 * ldc + gc)       = p0;
                *reinterpret_cast<__half2*>(Ch + (r0 + 8) * ldc + gc) = p1;
            } else {
                float2 p0, p1;
                p0.x = v[0]; p0.y = v[1];  p1.x = v[2]; p1.y = v[3];
                *reinterpret_cast<float2*>(Cf + r0 * ldc + gc)       = p0;
                *reinterpret_cast<float2*>(Cf + (r0 + 8) * ldc + gc) = p1;
            }
        }
    }
    }
}

// ---------------- x -> fp16 (elementwise) -----------------------------------
__global__ void cvt_x(const float4* __restrict__ x, uint4* __restrict__ xq)
{
    const size_t i = (size_t)blockIdx.x * blockDim.x + threadIdx.x;
    const float4 a = x[i * 2];
    const float4 b = x[i * 2 + 1];
    __half2 h0 = __floats2half2_rn(a.x, a.y);
    __half2 h1 = __floats2half2_rn(a.z, a.w);
    __half2 h2 = __floats2half2_rn(b.x, b.y);
    __half2 h3 = __floats2half2_rn(b.z, b.w);
    uint4 u;
    u.x = *reinterpret_cast<uint32_t*>(&h0);
    u.y = *reinterpret_cast<uint32_t*>(&h1);
    u.z = *reinterpret_cast<uint32_t*>(&h2);
    u.w = *reinterpret_cast<uint32_t*>(&h3);
    xq[i] = u;
}

// ---------------- weight prep: transpose [K,N] f32 -> [Np][Kp] f16 hi/lo ---
__global__ void prep_weight(const float* __restrict__ W, int K, int N,
                            f16* __restrict__ Wh, f16* __restrict__ Wl,
                            int Kp, int Np)
{
    __shared__ float t[32][33];
    const int k0 = blockIdx.x * 32, n0 = blockIdx.y * 32;
    const int tx = threadIdx.x, ty = threadIdx.y;     // (32, 8)
#pragma unroll
    for (int j = 0; j < 4; j++) {
        const int k = k0 + ty + j * 8, n = n0 + tx;
        t[ty + j * 8][tx] = (k < K && n < N) ? W[(size_t)k * N + n] : 0.0f;
    }
    __syncthreads();
#pragma unroll
    for (int j = 0; j < 4; j++) {
        const int n = n0 + ty + j * 8, k = k0 + tx;
        if (n < Np && k < Kp) {
            const float v = t[tx][ty + j * 8];
            const f16 h = __float2half_rn(v);
            Wh[(size_t)n * Kp + k] = h;
            Wl[(size_t)n * Kp + k] = __float2half_rn(v - __half2float(h));
        }
    }
}

// ------------- per-row heads: rho = tanh(h1@W22+b22), logs = h1@W23+b23 ----
__global__ void rho_logs_kernel(const f16* __restrict__ h1q,
                                const float* __restrict__ W22,
                                const float* __restrict__ b22,
                                const float* __restrict__ W23,
                                const float* __restrict__ b23,
                                float* __restrict__ rho_out,
                                float* __restrict__ logs_out)
{
    const int row  = blockIdx.x * blockDim.y + threadIdx.y;
    const int lane = threadIdx.x;
    const size_t base = (size_t)row * H_PAD;

    float a = 0.f, b = 0.f;
    for (int i = lane; i < H_DIM; i += 32) {
        const float h = __half2float(h1q[base + i]);
        a = fmaf(h, W22[i], a);
        b = fmaf(h, W23[i], b);
    }
#pragma unroll
    for (int o = 16; o > 0; o >>= 1) {
        a += __shfl_xor_sync(0xffffffffu, a, o);
        b += __shfl_xor_sync(0xffffffffu, b, o);
    }
    if (lane == 0) {
        const float logs = b + b23[0];
        rho_out[row]  = tanhf(a + b22[0]);
        logs_out[row] = logs;
        g_std[row]    = sqrtf(expf(logs));
    }
}

// ------------- z = cumsum(eps * std, axis=1) + mu, warp per row ------------
__global__ __launch_bounds__(256) void scan_kernel(
    const float* __restrict__ eps, const float* __restrict__ mu,
    f16* __restrict__ zq)
{
    const int warp = threadIdx.x >> 5, lane = threadIdx.x & 31;
    const int row  = blockIdx.x * 8 + warp;
    const float s  = g_std[row];
    const size_t base = (size_t)row * Z_DIM + lane * 16;

    float v[16];
#pragma unroll
    for (int q = 0; q < 4; q++) {
        const float4 e = *reinterpret_cast<const float4*>(eps + base + q * 4);
        v[q * 4 + 0] = e.x * s;  v[q * 4 + 1] = e.y * s;
        v[q * 4 + 2] = e.z * s;  v[q * 4 + 3] = e.w * s;
    }
#pragma unroll
    for (int q = 1; q < 16; q++) v[q] += v[q - 1];
    float tot = v[15];
#pragma unroll
    for (int o = 1; o < 32; o <<= 1) {
        const float n = __shfl_up_sync(0xffffffffu, tot, o);
        if (lane >= o) tot += n;
    }
    const float off = tot - v[15];        // exclusive prefix for this lane

    __half2 hp[8];
#pragma unroll
    for (int q = 0; q < 4; q++) {
        const float4 m = *reinterpret_cast<const float4*>(mu + base + q * 4);
        hp[q * 2]     = __floats2half2_rn(v[q * 4 + 0] + off + m.x,
                                          v[q * 4 + 1] + off + m.y);
        hp[q * 2 + 1] = __floats2half2_rn(v[q * 4 + 2] + off + m.z,
                                          v[q * 4 + 3] + off + m.w);
    }
    *reinterpret_cast<uint4*>(zq + base)     = *reinterpret_cast<uint4*>(&hp[0]);
    *reinterpret_cast<uint4*>(zq + base + 8) = *reinterpret_cast<uint4*>(&hp[4]);
}

// ---------------------------------------------------------------------------
extern "C" void kernel_launch(void* const* d_in, const int* in_sizes, int n_in,
                              void* d_out, int out_size)
{
    const float* x   = (const float*)d_in[0];
    const float* eps = (const float*)d_in[1];
    const float* W1  = (const float*)d_in[2];
    const float* b1  = (const float*)d_in[3];
    const float* W21 = (const float*)d_in[4];
    const float* b21 = (const float*)d_in[5];
    const float* W22 = (const float*)d_in[6];
    const float* b22 = (const float*)d_in[7];
    const float* W23 = (const float*)d_in[8];
    const float* b23 = (const float*)d_in[9];
    const float* W3  = (const float*)d_in[10];
    const float* b3  = (const float*)d_in[11];
    const float* W4  = (const float*)d_in[12];
    const float* b4  = (const float*)d_in[13];

    float* out       = (float*)d_out;
    float* out_recon = out;                                    // [B, 4096]
    float* out_mu    = out_recon + (size_t)B_ROWS * DATA_DIM;  // [B, 512]
    float* out_rho   = out_mu    + (size_t)B_ROWS * Z_DIM;     // [B, 1]
    float* out_logs  = out_rho   + B_ROWS;                     // [B, 1]

    f16 *xq, *h1q, *zq, *h3q;
    f16 *W1h, *W1l, *W21h, *W21l, *W3h, *W3l, *W4h, *W4l;
    cudaGetSymbolAddress((void**)&xq,   g_xq);
    cudaGetSymbolAddress((void**)&h1q,  g_h1q);
    cudaGetSymbolAddress((void**)&zq,   g_zq);
    cudaGetSymbolAddress((void**)&h3q,  g_h3q);
    cudaGetSymbolAddress((void**)&W1h,  g_W1h);
    cudaGetSymbolAddress((void**)&W1l,  g_W1l);
    cudaGetSymbolAddress((void**)&W21h, g_W21h);
    cudaGetSymbolAddress((void**)&W21l, g_W21l);
    cudaGetSymbolAddress((void**)&W3h,  g_W3h);
    cudaGetSymbolAddress((void**)&W3l,  g_W3l);
    cudaGetSymbolAddress((void**)&W4h,  g_W4h);
    cudaGetSymbolAddress((void**)&W4l,  g_W4l);

    const int smem64 = 2 * Geo<64>::STAGE;   // 110592
    const int smem32 = 2 * Geo<32>::STAGE;   // 61440
    cudaFuncSetAttribute(gemm_mma<1, 1, 64>, cudaFuncAttributeMaxDynamicSharedMemorySize, smem64);
    cudaFuncSetAttribute(gemm_mma<0, 0, 32>, cudaFuncAttributeMaxDynamicSharedMemorySize, smem32);
    cudaFuncSetAttribute(gemm_mma<2, 0, 32>, cudaFuncAttributeMaxDynamicSharedMemorySize, smem32);

    const dim3 pb(32, 8);

    // idx0: x -> fp16
    cvt_x<<<(B_ROWS * DATA_DIM / 8) / 256, 256>>>(
        (const float4*)x, (uint4*)xq);
    // idx1, idx2: weights needed by gemm1/gemm2
    prep_weight<<<dim3(DATA_DIM / 32, N1_PAD / 32), pb>>>(W1,  DATA_DIM, H_DIM, W1h,  W1l,  DATA_DIM, N1_PAD);
    prep_weight<<<dim3(H_PAD / 32,    Z_DIM / 32),  pb>>>(W21, H_DIM,    Z_DIM, W21h, W21l, H_PAD,    Z_DIM);

    // idx3 (ncu capture slot): h1 = relu(x @ W1 + b1) -> f16   [KC=64]
    gemm_mma<1, 1, 64><<<dim3(N1_PAD / 128, B_ROWS / 128), 256, smem64>>>(
        xq, DATA_DIM, W1h, W1l, DATA_DIM, b1,
        nullptr, h1q, H_PAD, H_DIM, DATA_DIM);

    // idx4: rho / logs / std
    rho_logs_kernel<<<B_ROWS / 8, dim3(32, 8)>>>(
        h1q, W22, b22, W23, b23, out_rho, out_logs);

    // idx5: mu = h1 @ W21 + b21 -> fp32 output   [KC=32, K=416]
    gemm_mma<0, 0, 32><<<dim3(Z_DIM / 128, B_ROWS / 128), 256, smem32>>>(
        h1q, H_PAD, W21h, W21l, H_PAD, b21,
        out_mu, nullptr, Z_DIM, Z_DIM, H_PAD);

    // idx6: z = cumsum(eps*std) + mu -> f16 (warp per row)
    scan_kernel<<<B_ROWS / 8, 256>>>(eps, out_mu, zq);

    // idx7: W3 prep, idx8: h3 = relu(z @ W3 + b3) -> f16   [KC=64, K=512]
    prep_weight<<<dim3(Z_DIM / 32, N1_PAD / 32), pb>>>(W3, Z_DIM, H_DIM, W3h, W3l, Z_DIM, N1_PAD);
    gemm_mma<1, 1, 64><<<dim3(N1_PAD / 128, B_ROWS / 128), 256, smem64>>>(
        zq, Z_DIM, W3h, W3l, Z_DIM, b3,
        nullptr, h3q, H_PAD, H_DIM, Z_DIM);

    // idx9: W4 prep, idx10: recon = sigmoid(h3 @ W4 + b4) -> fp32   [KC=32]
    prep_weight<<<dim3(H_PAD / 32, DATA_DIM / 32), pb>>>(W4, H_DIM, DATA_DIM, W4h, W4l, H_PAD, DATA_DIM);
    gemm_mma<2, 0, 32><<<dim3(DATA_DIM / 128, B_ROWS / 128), 256, smem32>>>(
        h3q, H_PAD, W4h, W4l, H_PAD, b4,
        out_recon, nullptr, DATA_DIM, DATA_DIM, H_PAD);
}